// round 1
// baseline (speedup 1.0000x reference)
#include <cuda_runtime.h>

// Problem constants
#define T   2048
#define H   2048
#define NE  8
#define F   1408
#define FS  2816

// GEMM tiling
#define TM  64
#define TN  64
#define TKK 16
#define CAPTILES 72            // 4096/64 row tiles + 8 alignment pads
#define CAP (CAPTILES * TM)    // 4608 bucket slots

// ---------------- device scratch (no allocations allowed) ----------------
__device__ int   g_cnt[NE];
__device__ int   g_fill[NE];
__device__ int   g_seg[NE];
__device__ int   g_tidx[T * 2];
__device__ float g_tw[T * 2];
__device__ int   g_btok[CAP];
__device__ float g_bw[CAP];
__device__ float g_h1[(size_t)CAP * F];     // routed intermediate  (~26 MB)
__device__ float g_h1s[(size_t)T * FS];     // shared intermediate  (~23 MB)

// ---------------- f32x2 packed-FMA helpers (sm_103a FFMA2) ----------------
__device__ __forceinline__ unsigned long long pack_dup(float a) {
    unsigned long long r;
    asm("mov.b64 %0, {%1, %1};" : "=l"(r) : "f"(a));
    return r;
}
__device__ __forceinline__ void fma_x2(unsigned long long& acc,
                                       unsigned long long a,
                                       unsigned long long b) {
    asm("fma.rn.f32x2 %0, %1, %2, %0;" : "+l"(acc) : "l"(a), "l"(b));
}
__device__ __forceinline__ float2 unpack2(unsigned long long v) {
    float2 f;
    asm("mov.b64 {%0, %1}, %2;" : "=f"(f.x), "=f"(f.y) : "l"(v));
    return f;
}

// ---------------- small kernels ----------------
__global__ void k_init() {
    int i = threadIdx.x;
    if (i < NE) { g_cnt[i] = 0; g_fill[i] = 0; }
}

// one warp per token: logits over 8 experts, softmax, top-2, normalize
__global__ void k_gate(const float* __restrict__ x, const float* __restrict__ gw) {
    int gt   = blockIdx.x * blockDim.x + threadIdx.x;
    int t    = gt >> 5;
    int lane = gt & 31;
    if (t >= T) return;
    const float* xr = x + (size_t)t * H;
    float acc[NE];
#pragma unroll
    for (int e = 0; e < NE; e++) acc[e] = 0.f;
    for (int i = lane; i < H; i += 32) {
        float xv = xr[i];
#pragma unroll
        for (int e = 0; e < NE; e++) acc[e] += xv * gw[e * H + i];
    }
#pragma unroll
    for (int e = 0; e < NE; e++) {
#pragma unroll
        for (int o = 16; o > 0; o >>= 1)
            acc[e] += __shfl_down_sync(0xffffffffu, acc[e], o);
    }
    if (lane == 0) {
        float m = acc[0];
#pragma unroll
        for (int e = 1; e < NE; e++) m = fmaxf(m, acc[e]);
        float p[NE], s = 0.f;
#pragma unroll
        for (int e = 0; e < NE; e++) { p[e] = expf(acc[e] - m); s += p[e]; }
        float inv = 1.f / s;
#pragma unroll
        for (int e = 0; e < NE; e++) p[e] *= inv;
        int i0 = 0; float v0 = p[0];
#pragma unroll
        for (int e = 1; e < NE; e++) if (p[e] > v0) { v0 = p[e]; i0 = e; }
        int i1 = -1; float v1 = -1.f;
#pragma unroll
        for (int e = 0; e < NE; e++) if (e != i0 && p[e] > v1) { v1 = p[e]; i1 = e; }
        float d = 1.f / (v0 + v1 + 1e-20f);
        g_tidx[t * 2 + 0] = i0; g_tw[t * 2 + 0] = v0 * d;
        g_tidx[t * 2 + 1] = i1; g_tw[t * 2 + 1] = v1 * d;
        atomicAdd(&g_cnt[i0], 1);
        atomicAdd(&g_cnt[i1], 1);
    }
}

__global__ void k_scan() {
    if (threadIdx.x == 0) {
        int acc = 0;
        for (int e = 0; e < NE; e++) {
            g_seg[e] = acc;
            acc += (g_cnt[e] + TM - 1) / TM * TM;
        }
    }
}

__global__ void k_scatter() {
    int t = blockIdx.x * blockDim.x + threadIdx.x;
    if (t >= T) return;
#pragma unroll
    for (int k = 0; k < 2; k++) {
        int e   = g_tidx[t * 2 + k];
        float w = g_tw[t * 2 + k];
        int pos = atomicAdd(&g_fill[e], 1);
        int slot = g_seg[e] + pos;
        g_btok[slot] = t;
        g_bw[slot]   = w;
    }
}

// ---------------- expert lookup for a routed row tile ----------------
__device__ __forceinline__ void find_expert(int row0, int& e_out, int& valid_out) {
    int e = -1, vr = 0;
    for (int i = 0; i < NE; i++) {
        int st = g_seg[i];
        int sz = (g_cnt[i] + TM - 1) / TM * TM;
        if (row0 >= st && row0 < st + sz) { e = i; vr = g_cnt[i] - (row0 - st); break; }
    }
    e_out = e; valid_out = vr;
}

// ================= GEMM 1: routed gate+up, fused SiLU =================
// h1[slot, F] = silu(x[tok] @ wg_e^T) * (x[tok] @ wu_e^T)
__global__ __launch_bounds__(256) void k_routed_upgate(
    const float* __restrict__ x, const float* __restrict__ wg,
    const float* __restrict__ wu) {
    __shared__ float As[TKK][TM];
    __shared__ float B0[TKK][TN];
    __shared__ float B1[TKK][TN];
    __shared__ int   stok[TM];
    __shared__ int   sh_e, sh_valid;

    int tid  = threadIdx.x;
    int row0 = blockIdx.y * TM;
    if (tid == 0) find_expert(row0, sh_e, sh_valid);
    __syncthreads();
    int e = sh_e;
    if (e < 0 || sh_valid <= 0) return;
    int nvalid = sh_valid > TM ? TM : sh_valid;
    if (tid < TM) stok[tid] = (tid < nvalid) ? g_btok[row0 + tid] : 0;
    __syncthreads();

    int lr = tid >> 2, lq = tid & 3;
    int tx = tid & 15, ty = tid >> 4;
    int col0 = blockIdx.x * TN;
    int atok = stok[lr];
    const float* ap  = x  + (size_t)atok * H + lq * 4;
    const float* bgp = wg + (size_t)e * F * H + (size_t)(col0 + lr) * H + lq * 4;
    const float* bup = wu + (size_t)e * F * H + (size_t)(col0 + lr) * H + lq * 4;

    unsigned long long accg[4][2], accu[4][2];
#pragma unroll
    for (int i = 0; i < 4; i++)
#pragma unroll
        for (int j = 0; j < 2; j++) { accg[i][j] = 0ull; accu[i][j] = 0ull; }

    for (int k0 = 0; k0 < H; k0 += TKK) {
        float4 av = *(const float4*)(ap + k0);
        float4 bg = *(const float4*)(bgp + k0);
        float4 bu = *(const float4*)(bup + k0);
        __syncthreads();
        As[lq * 4 + 0][lr] = av.x; As[lq * 4 + 1][lr] = av.y;
        As[lq * 4 + 2][lr] = av.z; As[lq * 4 + 3][lr] = av.w;
        B0[lq * 4 + 0][lr] = bg.x; B0[lq * 4 + 1][lr] = bg.y;
        B0[lq * 4 + 2][lr] = bg.z; B0[lq * 4 + 3][lr] = bg.w;
        B1[lq * 4 + 0][lr] = bu.x; B1[lq * 4 + 1][lr] = bu.y;
        B1[lq * 4 + 2][lr] = bu.z; B1[lq * 4 + 3][lr] = bu.w;
        __syncthreads();
#pragma unroll
        for (int kk = 0; kk < TKK; kk++) {
            float4 a = *(const float4*)&As[kk][ty * 4];
            ulonglong2 b0 = *(const ulonglong2*)&B0[kk][tx * 4];
            ulonglong2 b1 = *(const ulonglong2*)&B1[kk][tx * 4];
            unsigned long long ad[4] = {pack_dup(a.x), pack_dup(a.y),
                                        pack_dup(a.z), pack_dup(a.w)};
#pragma unroll
            for (int i = 0; i < 4; i++) {
                fma_x2(accg[i][0], ad[i], b0.x);
                fma_x2(accg[i][1], ad[i], b0.y);
                fma_x2(accu[i][0], ad[i], b1.x);
                fma_x2(accu[i][1], ad[i], b1.y);
            }
        }
    }
#pragma unroll
    for (int i = 0; i < 4; i++) {
        int r = ty * 4 + i;
        if (r < nvalid) {
            float* dst = g_h1 + (size_t)(row0 + r) * F + col0 + tx * 4;
#pragma unroll
            for (int j = 0; j < 2; j++) {
                float2 g = unpack2(accg[i][j]);
                float2 u = unpack2(accu[i][j]);
                dst[j * 2 + 0] = g.x * (1.f / (1.f + expf(-g.x))) * u.x;
                dst[j * 2 + 1] = g.y * (1.f / (1.f + expf(-g.y))) * u.y;
            }
        }
    }
}

// ================= GEMM 2: routed down, weighted atomic accumulate =================
__global__ __launch_bounds__(256) void k_routed_down(
    const float* __restrict__ wd, float* __restrict__ out) {
    __shared__ float As[TKK][TM];
    __shared__ float Bs[TKK][TN];
    __shared__ int   stok[TM];
    __shared__ float swt[TM];
    __shared__ int   sh_e, sh_valid;

    int tid  = threadIdx.x;
    int row0 = blockIdx.y * TM;
    if (tid == 0) find_expert(row0, sh_e, sh_valid);
    __syncthreads();
    int e = sh_e;
    if (e < 0 || sh_valid <= 0) return;
    int nvalid = sh_valid > TM ? TM : sh_valid;
    if (tid < TM) {
        bool v = tid < nvalid;
        stok[tid] = v ? g_btok[row0 + tid] : 0;
        swt[tid]  = v ? g_bw[row0 + tid]  : 0.f;
    }
    __syncthreads();

    int lr = tid >> 2, lq = tid & 3;
    int tx = tid & 15, ty = tid >> 4;
    int col0 = blockIdx.x * TN;
    const float* ap = g_h1 + (size_t)(row0 + lr) * F + lq * 4;
    const float* bp = wd + (size_t)e * H * F + (size_t)(col0 + lr) * F + lq * 4;

    unsigned long long acc[4][2];
#pragma unroll
    for (int i = 0; i < 4; i++) { acc[i][0] = 0ull; acc[i][1] = 0ull; }

    for (int k0 = 0; k0 < F; k0 += TKK) {
        float4 av = *(const float4*)(ap + k0);
        float4 bv = *(const float4*)(bp + k0);
        __syncthreads();
        As[lq * 4 + 0][lr] = av.x; As[lq * 4 + 1][lr] = av.y;
        As[lq * 4 + 2][lr] = av.z; As[lq * 4 + 3][lr] = av.w;
        Bs[lq * 4 + 0][lr] = bv.x; Bs[lq * 4 + 1][lr] = bv.y;
        Bs[lq * 4 + 2][lr] = bv.z; Bs[lq * 4 + 3][lr] = bv.w;
        __syncthreads();
#pragma unroll
        for (int kk = 0; kk < TKK; kk++) {
            float4 a = *(const float4*)&As[kk][ty * 4];
            ulonglong2 b = *(const ulonglong2*)&Bs[kk][tx * 4];
            unsigned long long ad[4] = {pack_dup(a.x), pack_dup(a.y),
                                        pack_dup(a.z), pack_dup(a.w)};
#pragma unroll
            for (int i = 0; i < 4; i++) {
                fma_x2(acc[i][0], ad[i], b.x);
                fma_x2(acc[i][1], ad[i], b.y);
            }
        }
    }
#pragma unroll
    for (int i = 0; i < 4; i++) {
        int r = ty * 4 + i;
        if (r < nvalid) {
            int tkn = stok[r];
            float w = swt[r];
            float* o = out + (size_t)tkn * H + col0 + tx * 4;
#pragma unroll
            for (int j = 0; j < 2; j++) {
                float2 v = unpack2(acc[i][j]);
                atomicAdd(&o[j * 2 + 0], w * v.x);
                atomicAdd(&o[j * 2 + 1], w * v.y);
            }
        }
    }
}

// ================= GEMM 3: shared gate+up, fused SiLU =================
__global__ __launch_bounds__(256) void k_shared_upgate(
    const float* __restrict__ x, const float* __restrict__ swg,
    const float* __restrict__ swu) {
    __shared__ float As[TKK][TM];
    __shared__ float B0[TKK][TN];
    __shared__ float B1[TKK][TN];

    int tid = threadIdx.x;
    int row0 = blockIdx.y * TM;
    int col0 = blockIdx.x * TN;
    int lr = tid >> 2, lq = tid & 3;
    int tx = tid & 15, ty = tid >> 4;
    const float* ap  = x   + (size_t)(row0 + lr) * H + lq * 4;
    const float* bgp = swg + (size_t)(col0 + lr) * H + lq * 4;
    const float* bup = swu + (size_t)(col0 + lr) * H + lq * 4;

    unsigned long long accg[4][2], accu[4][2];
#pragma unroll
    for (int i = 0; i < 4; i++)
#pragma unroll
        for (int j = 0; j < 2; j++) { accg[i][j] = 0ull; accu[i][j] = 0ull; }

    for (int k0 = 0; k0 < H; k0 += TKK) {
        float4 av = *(const float4*)(ap + k0);
        float4 bg = *(const float4*)(bgp + k0);
        float4 bu = *(const float4*)(bup + k0);
        __syncthreads();
        As[lq * 4 + 0][lr] = av.x; As[lq * 4 + 1][lr] = av.y;
        As[lq * 4 + 2][lr] = av.z; As[lq * 4 + 3][lr] = av.w;
        B0[lq * 4 + 0][lr] = bg.x; B0[lq * 4 + 1][lr] = bg.y;
        B0[lq * 4 + 2][lr] = bg.z; B0[lq * 4 + 3][lr] = bg.w;
        B1[lq * 4 + 0][lr] = bu.x; B1[lq * 4 + 1][lr] = bu.y;
        B1[lq * 4 + 2][lr] = bu.z; B1[lq * 4 + 3][lr] = bu.w;
        __syncthreads();
#pragma unroll
        for (int kk = 0; kk < TKK; kk++) {
            float4 a = *(const float4*)&As[kk][ty * 4];
            ulonglong2 b0 = *(const ulonglong2*)&B0[kk][tx * 4];
            ulonglong2 b1 = *(const ulonglong2*)&B1[kk][tx * 4];
            unsigned long long ad[4] = {pack_dup(a.x), pack_dup(a.y),
                                        pack_dup(a.z), pack_dup(a.w)};
#pragma unroll
            for (int i = 0; i < 4; i++) {
                fma_x2(accg[i][0], ad[i], b0.x);
                fma_x2(accg[i][1], ad[i], b0.y);
                fma_x2(accu[i][0], ad[i], b1.x);
                fma_x2(accu[i][1], ad[i], b1.y);
            }
        }
    }
#pragma unroll
    for (int i = 0; i < 4; i++) {
        int r = ty * 4 + i;
        float* dst = g_h1s + (size_t)(row0 + r) * FS + col0 + tx * 4;
#pragma unroll
        for (int j = 0; j < 2; j++) {
            float2 g = unpack2(accg[i][j]);
            float2 u = unpack2(accu[i][j]);
            dst[j * 2 + 0] = g.x * (1.f / (1.f + expf(-g.x))) * u.x;
            dst[j * 2 + 1] = g.y * (1.f / (1.f + expf(-g.y))) * u.y;
        }
    }
}

// ================= GEMM 4: shared down, plain store (initializes out) =================
__global__ __launch_bounds__(256) void k_shared_down(
    const float* __restrict__ swd, float* __restrict__ out) {
    __shared__ float As[TKK][TM];
    __shared__ float Bs[TKK][TN];

    int tid = threadIdx.x;
    int row0 = blockIdx.y * TM;
    int col0 = blockIdx.x * TN;
    int lr = tid >> 2, lq = tid & 3;
    int tx = tid & 15, ty = tid >> 4;
    const float* ap = g_h1s + (size_t)(row0 + lr) * FS + lq * 4;
    const float* bp = swd   + (size_t)(col0 + lr) * FS + lq * 4;

    unsigned long long acc[4][2];
#pragma unroll
    for (int i = 0; i < 4; i++) { acc[i][0] = 0ull; acc[i][1] = 0ull; }

    for (int k0 = 0; k0 < FS; k0 += TKK) {
        float4 av = *(const float4*)(ap + k0);
        float4 bv = *(const float4*)(bp + k0);
        __syncthreads();
        As[lq * 4 + 0][lr] = av.x; As[lq * 4 + 1][lr] = av.y;
        As[lq * 4 + 2][lr] = av.z; As[lq * 4 + 3][lr] = av.w;
        Bs[lq * 4 + 0][lr] = bv.x; Bs[lq * 4 + 1][lr] = bv.y;
        Bs[lq * 4 + 2][lr] = bv.z; Bs[lq * 4 + 3][lr] = bv.w;
        __syncthreads();
#pragma unroll
        for (int kk = 0; kk < TKK; kk++) {
            float4 a = *(const float4*)&As[kk][ty * 4];
            ulonglong2 b = *(const ulonglong2*)&Bs[kk][tx * 4];
            unsigned long long ad[4] = {pack_dup(a.x), pack_dup(a.y),
                                        pack_dup(a.z), pack_dup(a.w)};
#pragma unroll
            for (int i = 0; i < 4; i++) {
                fma_x2(acc[i][0], ad[i], b.x);
                fma_x2(acc[i][1], ad[i], b.y);
            }
        }
    }
#pragma unroll
    for (int i = 0; i < 4; i++) {
        int r = ty * 4 + i;
        float* o = out + (size_t)(row0 + r) * H + col0 + tx * 4;
#pragma unroll
        for (int j = 0; j < 2; j++) {
            float2 v = unpack2(acc[i][j]);
            o[j * 2 + 0] = v.x;
            o[j * 2 + 1] = v.y;
        }
    }
}

// ---------------- launch ----------------
extern "C" void kernel_launch(void* const* d_in, const int* in_sizes, int n_in,
                              void* d_out, int out_size) {
    const float* x   = (const float*)d_in[0];
    const float* gw  = (const float*)d_in[1];
    const float* wg  = (const float*)d_in[2];
    const float* wu  = (const float*)d_in[3];
    const float* wd  = (const float*)d_in[4];
    const float* swg = (const float*)d_in[5];
    const float* swu = (const float*)d_in[6];
    const float* swd = (const float*)d_in[7];
    float* out = (float*)d_out;

    k_init<<<1, 32>>>();
    k_gate<<<T / 8, 256>>>(x, gw);
    k_scan<<<1, 32>>>();
    k_scatter<<<(T + 255) / 256, 256>>>();

    // shared expert first: its down-proj initializes `out` with plain stores
    k_shared_upgate<<<dim3(FS / TN, T / TM), 256>>>(x, swg, swu);
    k_shared_down<<<dim3(H / TN, T / TM), 256>>>(swd, out);

    // routed experts accumulate on top via atomicAdd
    k_routed_upgate<<<dim3(F / TN, CAPTILES), 256>>>(x, wg, wu);
    k_routed_down<<<dim3(H / TN, CAPTILES), 256>>>(wd, out);
}